// round 4
// baseline (speedup 1.0000x reference)
#include <cuda_runtime.h>
#include <cuda_bf16.h>
#include <math.h>

// ---------------- problem constants ----------------
#define Bb 16
#define Cc 384
#define Hh 56
#define Ww 56
#define NHd 12
#define WS 7
#define SSh 3
#define MLPd 1536
#define Ntok 49          // tokens per window
#define nHW 8
#define nWin 64          // windows per image
#define HD 32            // head dim
#define TOT 50176        // B*H*W = total tokens
#define HWp 3136         // H*W

// ---------------- scratch (device globals; lifetimes aliased) ----------------
// g_xw:  phase A = LN1 output (windowed)   [TOT*C]
//        phase B = attention output        [TOT*C]
//        phase C = LN2 output              [TOT*C]
// g_big: phase A = qkv                     [TOT*3C]
//        phase B = fc1 output              [TOT*MLP]
// g_x2:  proj+residual result (token-major)[TOT*C]
__device__ float g_xw [(size_t)TOT * Cc];
__device__ float g_big[(size_t)TOT * MLPd];
__device__ float g_x2 [(size_t)TOT * Cc];

// ---------------- helpers ----------------
__device__ __forceinline__ float warpSum(float v) {
    #pragma unroll
    for (int o = 16; o; o >>= 1) v += __shfl_xor_sync(0xffffffffu, v, o);
    return v;
}

// ---------------- K1: LN1 + shift + window partition ----------------
__global__ void ln1_window_kernel(const float* __restrict__ x,
                                  const float* __restrict__ g,
                                  const float* __restrict__ b)
{
    int t = blockIdx.x;               // token = bb*3136 + h*56 + w
    int bb = t / HWp, hw = t % HWp;
    int h = hw / Ww, w = hw % Ww;
    int tid = threadIdx.x;            // 128 threads

    float vals[3];
    float s = 0.f, s2 = 0.f;
    #pragma unroll
    for (int i = 0; i < 3; i++) {
        int c = tid + i * 128;
        float v = x[((size_t)bb * Cc + c) * HWp + hw];
        vals[i] = v; s += v; s2 += v * v;
    }
    s = warpSum(s); s2 = warpSum(s2);
    __shared__ float rs[4], rs2[4];
    int warp = tid >> 5, lane = tid & 31;
    if (lane == 0) { rs[warp] = s; rs2[warp] = s2; }
    __syncthreads();
    float S = rs[0] + rs[1] + rs[2] + rs[3];
    float S2 = rs2[0] + rs2[1] + rs2[2] + rs2[3];
    float mean = S * (1.0f / Cc);
    float var = S2 * (1.0f / Cc) - mean * mean;
    float inv = rsqrtf(var + 1e-5f);

    // shift: xs[h2] = xh[h2+3 mod 56]  =>  this token lands at h2 = (h-3) mod 56
    int h2 = h - SSh; if (h2 < 0) h2 += Hh;
    int w2 = w - SSh; if (w2 < 0) w2 += Ww;
    int wh = h2 / WS, r = h2 % WS, ww = w2 / WS, cw = w2 % WS;
    int win = bb * nWin + wh * nHW + ww;
    size_t dst = ((size_t)win * Ntok + r * WS + cw) * Cc;
    #pragma unroll
    for (int i = 0; i < 3; i++) {
        int c = tid + i * 128;
        g_xw[dst + c] = (vals[i] - mean) * inv * g[c] + b[c];
    }
}

// ---------------- K5: LN2 (token-major in/out) ----------------
__global__ void ln2_kernel(const float* __restrict__ in,
                           const float* __restrict__ g,
                           const float* __restrict__ b,
                           float* __restrict__ out)
{
    int t = blockIdx.x;
    int tid = threadIdx.x;
    const float* row = in + (size_t)t * Cc;
    float vals[3];
    float s = 0.f, s2 = 0.f;
    #pragma unroll
    for (int i = 0; i < 3; i++) {
        float v = row[tid + i * 128];
        vals[i] = v; s += v; s2 += v * v;
    }
    s = warpSum(s); s2 = warpSum(s2);
    __shared__ float rs[4], rs2[4];
    int warp = tid >> 5, lane = tid & 31;
    if (lane == 0) { rs[warp] = s; rs2[warp] = s2; }
    __syncthreads();
    float S = rs[0] + rs[1] + rs[2] + rs[3];
    float S2 = rs2[0] + rs2[1] + rs2[2] + rs2[3];
    float mean = S * (1.0f / Cc);
    float var = S2 * (1.0f / Cc) - mean * mean;
    float inv = rsqrtf(var + 1e-5f);
    float* orow = out + (size_t)t * Cc;
    #pragma unroll
    for (int i = 0; i < 3; i++) {
        int c = tid + i * 128;
        orow[c] = (vals[i] - mean) * inv * g[c] + b[c];
    }
}

// ---------------- K3: windowed attention ----------------
__device__ __forceinline__ int grp(int wsel, int r) {
    return (wsel < 7) ? 0 : ((r < 4) ? 1 : 2);
}

__global__ void attn_kernel(const float* __restrict__ qkv,
                            float* __restrict__ attn_out)
{
    int blk = blockIdx.x;                 // win*12 + head
    int win = blk / NHd, head = blk % NHd;
    __shared__ float q[Ntok][HD + 1], kk[Ntok][HD + 1], vv[Ntok][HD + 1];
    __shared__ float S[Ntok][Ntok + 1];
    int tid = threadIdx.x;                // 256
    const float scale = 0.17677669529663687f;   // HD^-0.5
    size_t base = (size_t)win * Ntok * (3 * Cc) + (size_t)head * HD;

    for (int idx = tid; idx < Ntok * HD; idx += 256) {
        int n = idx >> 5, d = idx & 31;
        size_t rb = base + (size_t)n * (3 * Cc);
        q[n][d]  = qkv[rb + d] * scale;
        kk[n][d] = qkv[rb + Cc + d];
        vv[n][d] = qkv[rb + 2 * Cc + d];
    }
    __syncthreads();

    int wi = win & (nWin - 1);
    int wh = wi >> 3, ww = wi & 7;

    for (int idx = tid; idx < Ntok * Ntok; idx += 256) {
        int i = idx / Ntok, j = idx % Ntok;
        float acc = 0.f;
        #pragma unroll
        for (int d = 0; d < HD; d++) acc += q[i][d] * kk[j][d];
        int ri = i / WS, ci = i % WS, rj = j / WS, cj = j % WS;
        int gi = grp(wh, ri) * 3 + grp(ww, ci);
        int gj = grp(wh, rj) * 3 + grp(ww, cj);
        if (gi != gj) acc -= 100.0f;
        S[i][j] = acc;
    }
    __syncthreads();

    if (tid < Ntok) {
        float m = -1e30f;
        #pragma unroll 7
        for (int j = 0; j < Ntok; j++) m = fmaxf(m, S[tid][j]);
        float sum = 0.f;
        #pragma unroll 7
        for (int j = 0; j < Ntok; j++) { float e = __expf(S[tid][j] - m); S[tid][j] = e; sum += e; }
        float rinv = 1.0f / sum;
        #pragma unroll 7
        for (int j = 0; j < Ntok; j++) S[tid][j] *= rinv;
    }
    __syncthreads();

    for (int idx = tid; idx < Ntok * HD; idx += 256) {
        int i = idx >> 5, d = idx & 31;
        float acc = 0.f;
        #pragma unroll 7
        for (int j = 0; j < Ntok; j++) acc += S[i][j] * vv[j][d];
        attn_out[((size_t)win * Ntok + i) * Cc + head * HD + d] = acc;
    }
}

// ---------------- 64x64 register-blocked SGEMM with fused epilogues ----------
// MODE 0: C = A@W + bias                               (qkv)
// MODE 1: C = gelu(A@W + bias)                         (fc1)
// MODE 2: window-reverse + residual(x NCHW) -> x2 tok-major (proj)
// MODE 3: residual(x2) -> output NCHW                  (fc2)
template<int MODE>
__global__ __launch_bounds__(256)
void gemm64(const float* __restrict__ A, const float* __restrict__ Wt,
            const float* __restrict__ bias, float* __restrict__ Cout,
            const float* __restrict__ aux, int M, int Nc, int K)
{
    __shared__ float As[16][64];
    __shared__ float Bs[16][68];
    int tid = threadIdx.x;
    int tx = tid & 15, ty = tid >> 4;
    int rowBase = blockIdx.y * 64;
    int colBase = blockIdx.x * 64;
    float acc[4][4] = {};

    for (int k0 = 0; k0 < K; k0 += 16) {
        {
            int r = tid >> 2;
            int c4 = (tid & 3) * 4;
            float4 a = *reinterpret_cast<const float4*>(&A[(size_t)(rowBase + r) * K + k0 + c4]);
            As[c4 + 0][r] = a.x; As[c4 + 1][r] = a.y;
            As[c4 + 2][r] = a.z; As[c4 + 3][r] = a.w;
        }
        {
            int r = tid >> 4;
            int c4 = (tid & 15) * 4;
            float4 b = *reinterpret_cast<const float4*>(&Wt[(size_t)(k0 + r) * Nc + colBase + c4]);
            *reinterpret_cast<float4*>(&Bs[r][c4]) = b;
        }
        __syncthreads();
        #pragma unroll
        for (int k = 0; k < 16; k++) {
            float a0[4], b0[4];
            #pragma unroll
            for (int i = 0; i < 4; i++) a0[i] = As[k][ty * 4 + i];
            #pragma unroll
            for (int j = 0; j < 4; j++) b0[j] = Bs[k][tx * 4 + j];
            #pragma unroll
            for (int i = 0; i < 4; i++)
                #pragma unroll
                for (int j = 0; j < 4; j++) acc[i][j] += a0[i] * b0[j];
        }
        __syncthreads();
    }

    int row0 = rowBase + ty * 4;
    int col0 = colBase + tx * 4;
    #pragma unroll
    for (int i = 0; i < 4; i++) {
        int t = row0 + i;
        int bb = 0, hw = 0;
        if (MODE == 2) {
            int w = t / Ntok, n = t % Ntok;
            bb = w >> 6; int wi = w & 63;
            int wh = wi >> 3, ww = wi & 7;
            int r = n / WS, cc = n % WS;
            int hh = wh * WS + r + SSh;  if (hh >= Hh) hh -= Hh;
            int wc = ww * WS + cc + SSh; if (wc >= Ww) wc -= Ww;
            hw = hh * Ww + wc;
        } else if (MODE == 3) {
            bb = t / HWp; hw = t % HWp;
        }
        #pragma unroll
        for (int j = 0; j < 4; j++) {
            int col = col0 + j;
            float v = acc[i][j] + bias[col];
            if (MODE == 0) {
                Cout[(size_t)t * Nc + col] = v;
            } else if (MODE == 1) {
                v = 0.5f * v * (1.0f + erff(v * 0.70710678118654752f));
                Cout[(size_t)t * Nc + col] = v;
            } else if (MODE == 2) {
                v += aux[((size_t)bb * Cc + col) * HWp + hw];        // + shortcut x (NCHW)
                Cout[((size_t)bb * HWp + hw) * Cc + col] = v;        // x2 token-major
            } else { // MODE == 3
                v += aux[(size_t)t * Cc + col];                      // + x2
                Cout[((size_t)bb * Cc + col) * HWp + hw] = v;        // output NCHW
            }
        }
    }
}

// ---------------- launch ----------------
extern "C" void kernel_launch(void* const* d_in, const int* in_sizes, int n_in,
                              void* d_out, int out_size)
{
    const float* x       = (const float*)d_in[0];
    const float* norm1_g = (const float*)d_in[1];
    const float* norm1_b = (const float*)d_in[2];
    const float* qkv_w   = (const float*)d_in[3];
    const float* qkv_b   = (const float*)d_in[4];
    const float* proj_w  = (const float*)d_in[5];
    const float* proj_b  = (const float*)d_in[6];
    const float* norm2_g = (const float*)d_in[7];
    const float* norm2_b = (const float*)d_in[8];
    const float* fc1_w   = (const float*)d_in[9];
    const float* fc1_b   = (const float*)d_in[10];
    const float* fc2_w   = (const float*)d_in[11];
    const float* fc2_b   = (const float*)d_in[12];
    float* out = (float*)d_out;

    float *xw, *big, *x2b;
    cudaGetSymbolAddress((void**)&xw,  g_xw);
    cudaGetSymbolAddress((void**)&big, g_big);
    cudaGetSymbolAddress((void**)&x2b, g_x2);

    // 1. LN1 + shift + window partition -> xw
    ln1_window_kernel<<<TOT, 128>>>(x, norm1_g, norm1_b);

    // 2. QKV GEMM: [50176,384] @ [384,1152] -> big
    gemm64<0><<<dim3(1152 / 64, TOT / 64), 256>>>(xw, qkv_w, qkv_b, big, nullptr,
                                                  TOT, 3 * Cc, Cc);

    // 3. windowed attention: big(qkv) -> xw (attn out; xw's LN data is dead now)
    attn_kernel<<<(TOT / Ntok) * NHd, 256>>>(big, xw);

    // 4. proj GEMM + window reverse + residual -> x2 (token-major)
    gemm64<2><<<dim3(Cc / 64, TOT / 64), 256>>>(xw, proj_w, proj_b, x2b, x,
                                                TOT, Cc, Cc);

    // 5. LN2: x2 -> xw (attn out dead now)
    ln2_kernel<<<TOT, 128>>>(x2b, norm2_g, norm2_b, xw);

    // 6. FC1 + GELU: [50176,384] @ [384,1536] -> big (qkv dead now)
    gemm64<1><<<dim3(MLPd / 64, TOT / 64), 256>>>(xw, fc1_w, fc1_b, big, nullptr,
                                                  TOT, MLPd, Cc);

    // 7. FC2 + residual + NCHW store: [50176,1536] @ [1536,384] -> out
    gemm64<3><<<dim3(Cc / 64, TOT / 64), 256>>>(big, fc2_w, fc2_b, out, x2b,
                                                TOT, Cc, MLPd);
}

// round 8
// speedup vs baseline: 1.1289x; 1.1289x over previous
#include <cuda_runtime.h>
#include <cuda_bf16.h>
#include <math.h>

// ---------------- problem constants ----------------
#define Bb 16
#define Cc 384
#define Hh 56
#define Ww 56
#define NHd 12
#define WS 7
#define SSh 3
#define MLPd 1536
#define Ntok 49          // tokens per window
#define nHW 8
#define nWin 64          // windows per image
#define HD 32            // head dim
#define TOT 50176        // B*H*W = total tokens
#define HWp 3136         // H*W

// ---------------- scratch (device globals; lifetimes aliased) ----------------
__device__ float g_xw [(size_t)TOT * Cc];    // LN1-out / attn-out / LN2-out
__device__ float g_big[(size_t)TOT * MLPd];  // qkv / fc1-out
__device__ float g_x2 [(size_t)TOT * Cc];    // proj+residual (token-major)

// ---------------- helpers ----------------
__device__ __forceinline__ float warpSum(float v) {
    #pragma unroll
    for (int o = 16; o; o >>= 1) v += __shfl_xor_sync(0xffffffffu, v, o);
    return v;
}

// ---------------- K1: LN1 + shift + window partition ----------------
__global__ void ln1_window_kernel(const float* __restrict__ x,
                                  const float* __restrict__ g,
                                  const float* __restrict__ b)
{
    int t = blockIdx.x;               // token = bb*3136 + h*56 + w
    int bb = t / HWp, hw = t % HWp;
    int h = hw / Ww, w = hw % Ww;
    int tid = threadIdx.x;            // 128 threads

    float vals[3];
    float s = 0.f, s2 = 0.f;
    #pragma unroll
    for (int i = 0; i < 3; i++) {
        int c = tid + i * 128;
        float v = x[((size_t)bb * Cc + c) * HWp + hw];
        vals[i] = v; s += v; s2 += v * v;
    }
    s = warpSum(s); s2 = warpSum(s2);
    __shared__ float rs[4], rs2[4];
    int warp = tid >> 5, lane = tid & 31;
    if (lane == 0) { rs[warp] = s; rs2[warp] = s2; }
    __syncthreads();
    float S = rs[0] + rs[1] + rs[2] + rs[3];
    float S2 = rs2[0] + rs2[1] + rs2[2] + rs2[3];
    float mean = S * (1.0f / Cc);
    float var = S2 * (1.0f / Cc) - mean * mean;
    float inv = rsqrtf(var + 1e-5f);

    int h2 = h - SSh; if (h2 < 0) h2 += Hh;
    int w2 = w - SSh; if (w2 < 0) w2 += Ww;
    int wh = h2 / WS, r = h2 % WS, ww = w2 / WS, cw = w2 % WS;
    int win = bb * nWin + wh * nHW + ww;
    size_t dst = ((size_t)win * Ntok + r * WS + cw) * Cc;
    #pragma unroll
    for (int i = 0; i < 3; i++) {
        int c = tid + i * 128;
        g_xw[dst + c] = (vals[i] - mean) * inv * g[c] + b[c];
    }
}

// ---------------- K5: LN2 (token-major in/out) ----------------
__global__ void ln2_kernel(const float* __restrict__ in,
                           const float* __restrict__ g,
                           const float* __restrict__ b,
                           float* __restrict__ out)
{
    int t = blockIdx.x;
    int tid = threadIdx.x;
    const float* row = in + (size_t)t * Cc;
    float vals[3];
    float s = 0.f, s2 = 0.f;
    #pragma unroll
    for (int i = 0; i < 3; i++) {
        float v = row[tid + i * 128];
        vals[i] = v; s += v; s2 += v * v;
    }
    s = warpSum(s); s2 = warpSum(s2);
    __shared__ float rs[4], rs2[4];
    int warp = tid >> 5, lane = tid & 31;
    if (lane == 0) { rs[warp] = s; rs2[warp] = s2; }
    __syncthreads();
    float S = rs[0] + rs[1] + rs[2] + rs[3];
    float S2 = rs2[0] + rs2[1] + rs2[2] + rs2[3];
    float mean = S * (1.0f / Cc);
    float var = S2 * (1.0f / Cc) - mean * mean;
    float inv = rsqrtf(var + 1e-5f);
    float* orow = out + (size_t)t * Cc;
    #pragma unroll
    for (int i = 0; i < 3; i++) {
        int c = tid + i * 128;
        orow[c] = (vals[i] - mean) * inv * g[c] + b[c];
    }
}

// ---------------- K3: windowed attention ----------------
__device__ __forceinline__ int grp(int wsel, int r) {
    return (wsel < 7) ? 0 : ((r < 4) ? 1 : 2);
}

__global__ void attn_kernel(const float* __restrict__ qkv,
                            float* __restrict__ attn_out)
{
    int blk = blockIdx.x;                 // win*12 + head
    int win = blk / NHd, head = blk % NHd;
    __shared__ float q[Ntok][HD + 1], kk[Ntok][HD + 1], vv[Ntok][HD + 1];
    __shared__ float S[Ntok][Ntok + 1];
    int tid = threadIdx.x;                // 256
    const float scale = 0.17677669529663687f;   // HD^-0.5
    size_t base = (size_t)win * Ntok * (3 * Cc) + (size_t)head * HD;

    for (int idx = tid; idx < Ntok * HD; idx += 256) {
        int n = idx >> 5, d = idx & 31;
        size_t rb = base + (size_t)n * (3 * Cc);
        q[n][d]  = qkv[rb + d] * scale;
        kk[n][d] = qkv[rb + Cc + d];
        vv[n][d] = qkv[rb + 2 * Cc + d];
    }
    __syncthreads();

    int wi = win & (nWin - 1);
    int wh = wi >> 3, ww = wi & 7;

    for (int idx = tid; idx < Ntok * Ntok; idx += 256) {
        int i = idx / Ntok, j = idx % Ntok;
        float acc = 0.f;
        #pragma unroll
        for (int d = 0; d < HD; d++) acc += q[i][d] * kk[j][d];
        int ri = i / WS, ci = i % WS, rj = j / WS, cj = j % WS;
        int gi = grp(wh, ri) * 3 + grp(ww, ci);
        int gj = grp(wh, rj) * 3 + grp(ww, cj);
        if (gi != gj) acc -= 100.0f;
        S[i][j] = acc;
    }
    __syncthreads();

    if (tid < Ntok) {
        float m = -1e30f;
        #pragma unroll 7
        for (int j = 0; j < Ntok; j++) m = fmaxf(m, S[tid][j]);
        float sum = 0.f;
        #pragma unroll 7
        for (int j = 0; j < Ntok; j++) { float e = __expf(S[tid][j] - m); S[tid][j] = e; sum += e; }
        float rinv = 1.0f / sum;
        #pragma unroll 7
        for (int j = 0; j < Ntok; j++) S[tid][j] *= rinv;
    }
    __syncthreads();

    for (int idx = tid; idx < Ntok * HD; idx += 256) {
        int i = idx >> 5, d = idx & 31;
        float acc = 0.f;
        #pragma unroll 7
        for (int j = 0; j < Ntok; j++) acc += S[i][j] * vv[j][d];
        attn_out[((size_t)win * Ntok + i) * Cc + head * HD + d] = acc;
    }
}

// ------------- 128x128 register-blocked SGEMM (8x8/thread), fused epilogues --
// MODE 0: C = A@W + bias                               (qkv)
// MODE 1: C = gelu(A@W + bias)                         (fc1)
// MODE 2: window-reverse + residual(x NCHW) -> x2 tok-major (proj)
// MODE 3: residual(x2) -> output NCHW                  (fc2)
template<int MODE>
__global__ __launch_bounds__(256, 2)
void gemm128(const float* __restrict__ A, const float* __restrict__ Wt,
             const float* __restrict__ bias, float* __restrict__ Cout,
             const float* __restrict__ aux, int M, int Nc, int K)
{
    __shared__ float As[16][128];   // [k][row]
    __shared__ float Bs[16][128];   // [k][col]
    int tid = threadIdx.x;
    int tx = tid & 15, ty = tid >> 4;       // 16x16 threads, 8x8 each
    int rowBase = blockIdx.y * 128;
    int colBase = blockIdx.x * 128;
    float acc[8][8] = {};

    for (int k0 = 0; k0 < K; k0 += 16) {
        // load A tile: rows rowBase..+127, cols k0..+15 -> As[k][row]
        {
            int r = tid >> 1;                    // 0..127
            int c0 = (tid & 1) * 8;              // 0 or 8
            const float* ap = &A[(size_t)(rowBase + r) * K + k0 + c0];
            float4 a0 = *reinterpret_cast<const float4*>(ap);
            float4 a1 = *reinterpret_cast<const float4*>(ap + 4);
            As[c0 + 0][r] = a0.x; As[c0 + 1][r] = a0.y;
            As[c0 + 2][r] = a0.z; As[c0 + 3][r] = a0.w;
            As[c0 + 4][r] = a1.x; As[c0 + 5][r] = a1.y;
            As[c0 + 6][r] = a1.z; As[c0 + 7][r] = a1.w;
        }
        // load B tile: rows k0..+15, cols colBase..+127 -> Bs[k][col]
        {
            int kr = tid >> 4;                   // 0..15
            int c0 = (tid & 15) * 8;             // 0..120 step 8
            const float* bp = &Wt[(size_t)(k0 + kr) * Nc + colBase + c0];
            float4 b0 = *reinterpret_cast<const float4*>(bp);
            float4 b1 = *reinterpret_cast<const float4*>(bp + 4);
            *reinterpret_cast<float4*>(&Bs[kr][c0])     = b0;
            *reinterpret_cast<float4*>(&Bs[kr][c0 + 4]) = b1;
        }
        __syncthreads();
        #pragma unroll
        for (int k = 0; k < 16; k++) {
            float a0[8], b0[8];
            *reinterpret_cast<float4*>(&a0[0]) = *reinterpret_cast<const float4*>(&As[k][ty * 8]);
            *reinterpret_cast<float4*>(&a0[4]) = *reinterpret_cast<const float4*>(&As[k][ty * 8 + 4]);
            *reinterpret_cast<float4*>(&b0[0]) = *reinterpret_cast<const float4*>(&Bs[k][tx * 8]);
            *reinterpret_cast<float4*>(&b0[4]) = *reinterpret_cast<const float4*>(&Bs[k][tx * 8 + 4]);
            #pragma unroll
            for (int i = 0; i < 8; i++)
                #pragma unroll
                for (int j = 0; j < 8; j++) acc[i][j] += a0[i] * b0[j];
        }
        __syncthreads();
    }

    int row0 = rowBase + ty * 8;
    int col0 = colBase + tx * 8;
    #pragma unroll
    for (int i = 0; i < 8; i++) {
        int t = row0 + i;
        int bb = 0, hw = 0;
        if (MODE == 2) {
            int w = t / Ntok, n = t % Ntok;
            bb = w >> 6; int wi = w & 63;
            int wh = wi >> 3, ww = wi & 7;
            int r = n / WS, cc = n % WS;
            int hh = wh * WS + r + SSh;  if (hh >= Hh) hh -= Hh;
            int wc = ww * WS + cc + SSh; if (wc >= Ww) wc -= Ww;
            hw = hh * Ww + wc;
        } else if (MODE == 3) {
            bb = t / HWp; hw = t % HWp;
        }
        #pragma unroll
        for (int j = 0; j < 8; j++) {
            int col = col0 + j;
            float v = acc[i][j] + bias[col];
            if (MODE == 0) {
                Cout[(size_t)t * Nc + col] = v;
            } else if (MODE == 1) {
                v = 0.5f * v * (1.0f + erff(v * 0.70710678118654752f));
                Cout[(size_t)t * Nc + col] = v;
            } else if (MODE == 2) {
                v += aux[((size_t)bb * Cc + col) * HWp + hw];        // + shortcut x (NCHW)
                Cout[((size_t)bb * HWp + hw) * Cc + col] = v;        // x2 token-major
            } else { // MODE == 3
                v += aux[(size_t)t * Cc + col];                      // + x2
                Cout[((size_t)bb * Cc + col) * HWp + hw] = v;        // output NCHW
            }
        }
    }
}

// ---------------- launch ----------------
extern "C" void kernel_launch(void* const* d_in, const int* in_sizes, int n_in,
                              void* d_out, int out_size)
{
    const float* x       = (const float*)d_in[0];
    const float* norm1_g = (const float*)d_in[1];
    const float* norm1_b = (const float*)d_in[2];
    const float* qkv_w   = (const float*)d_in[3];
    const float* qkv_b   = (const float*)d_in[4];
    const float* proj_w  = (const float*)d_in[5];
    const float* proj_b  = (const float*)d_in[6];
    const float* norm2_g = (const float*)d_in[7];
    const float* norm2_b = (const float*)d_in[8];
    const float* fc1_w   = (const float*)d_in[9];
    const float* fc1_b   = (const float*)d_in[10];
    const float* fc2_w   = (const float*)d_in[11];
    const float* fc2_b   = (const float*)d_in[12];
    float* out = (float*)d_out;

    float *xw, *big, *x2b;
    cudaGetSymbolAddress((void**)&xw,  g_xw);
    cudaGetSymbolAddress((void**)&big, g_big);
    cudaGetSymbolAddress((void**)&x2b, g_x2);

    // 1. LN1 + shift + window partition -> xw
    ln1_window_kernel<<<TOT, 128>>>(x, norm1_g, norm1_b);

    // 2. QKV GEMM: [50176,384] @ [384,1152] -> big
    gemm128<0><<<dim3(1152 / 128, TOT / 128), 256>>>(xw, qkv_w, qkv_b, big, nullptr,
                                                     TOT, 3 * Cc, Cc);

    // 3. windowed attention: big(qkv) -> xw
    attn_kernel<<<(TOT / Ntok) * NHd, 256>>>(big, xw);

    // 4. proj GEMM + window reverse + residual -> x2 (token-major)
    gemm128<2><<<dim3(Cc / 128, TOT / 128), 256>>>(xw, proj_w, proj_b, x2b, x,
                                                   TOT, Cc, Cc);

    // 5. LN2: x2 -> xw
    ln2_kernel<<<TOT, 128>>>(x2b, norm2_g, norm2_b, xw);

    // 6. FC1 + GELU: [50176,384] @ [384,1536] -> big
    gemm128<1><<<dim3(MLPd / 128, TOT / 128), 256>>>(xw, fc1_w, fc1_b, big, nullptr,
                                                     TOT, MLPd, Cc);

    // 7. FC2 + residual + NCHW store: [50176,1536] @ [1536,384] -> out
    gemm128<3><<<dim3(Cc / 128, TOT / 128), 256>>>(big, fc2_w, fc2_b, out, x2b,
                                                   TOT, Cc, MLPd);
}